// round 16
// baseline (speedup 1.0000x reference)
#include <cuda_runtime.h>
#include <cuda_fp16.h>
#include <cstdint>

// AutoregressiveNetwork via HMMA mma.sync m16n8k16 fp16 + ldmatrix (sm_80 PTX;
// tcgen05 unavailable at compute_103). 63 masked MLPs [B,k]->64->64->2.
// R16: CTA = (net, 512 rows) = 4 row-tiles through a 2-slot x ring with
// software prefetch (tile i+2 issued as soon as tile i's x reads finish), so
// steady-state staging latency hides behind compute. 2016 CTAs (4.5 waves),
// weights staged once per CTA. SMEM/regs unchanged from R15: 3 CTAs/SM.

#define BATCHN 16384
#define TPB    128

#define SO_XH0  0        // x ring slot 0 : 128 rows * 128B
#define SO_XH1  16384    // x ring slot 1
#define SO_W1   32768    // W1 [j][n] fp16 (j>=k zeroed); only kt1*2KB copied
#define SO_W2   40960    // 8192
#define SO_W3F  49152    // W3 fp16 image: 64 rows * 32B (cols>=2 zero)
#define SO_B1   51200    // 64 floats
#define SO_B2   51456
#define SO_B3   51712    // float2
#define SO_MB0  51720
#define SO_MB1  51728
#define SMEM_BYTES 51736

#define SW(o) ((o) ^ (((o) >> 3) & 0x70))   // SW128 swizzle (128B rows)

typedef unsigned long long u64;

// ---- precomputed swizzled fp16 images (device scratch) ----
__device__ __align__(16) char gXH[128 * 16384];   // per 128-row tile
__device__ __align__(16) char gW1H[63 * 8192];    // per net, causal-masked
__device__ __align__(16) char gW2H[63 * 8192];
__device__ __align__(16) char gW3F[63 * 2048];    // per net, L3 B image

static __device__ __forceinline__ uint32_t smem_u32(const void* p) {
    uint32_t a;
    asm("{ .reg .u64 t; cvta.to.shared.u64 t, %1; cvt.u32.u64 %0, t; }" : "=r"(a) : "l"(p));
    return a;
}
static __device__ __forceinline__ uint32_t h2pack(float a, float b) {
    __half2 h = __floats2half2_rn(a, b);
    return *(uint32_t*)&h;
}
static __device__ __forceinline__ void mma16816(float* d, const uint32_t* a,
                                                uint32_t b0, uint32_t b1) {
    asm volatile(
        "mma.sync.aligned.m16n8k16.row.col.f32.f16.f16.f32 "
        "{%0,%1,%2,%3}, {%4,%5,%6,%7}, {%8,%9}, {%0,%1,%2,%3};"
        : "+f"(d[0]), "+f"(d[1]), "+f"(d[2]), "+f"(d[3])
        : "r"(a[0]), "r"(a[1]), "r"(a[2]), "r"(a[3]), "r"(b0), "r"(b1));
}
static __device__ __forceinline__ void ldsm_x4(uint32_t* r, uint32_t addr) {
    asm volatile("ldmatrix.sync.aligned.m8n8.x4.shared.b16 {%0,%1,%2,%3}, [%4];"
        : "=r"(r[0]), "=r"(r[1]), "=r"(r[2]), "=r"(r[3]) : "r"(addr));
}
static __device__ __forceinline__ void ldsm_x4t(uint32_t* r, uint32_t addr) {
    asm volatile("ldmatrix.sync.aligned.m8n8.x4.trans.shared.b16 {%0,%1,%2,%3}, [%4];"
        : "=r"(r[0]), "=r"(r[1]), "=r"(r[2]), "=r"(r[3]) : "r"(addr));
}
static __device__ __forceinline__ void bulk_cp(uint32_t dst, const void* src,
                                               uint32_t bytes, uint32_t mbar) {
    asm volatile(
        "cp.async.bulk.shared::cluster.global.mbarrier::complete_tx::bytes "
        "[%0], [%1], %2, [%3];"
        :: "r"(dst), "l"(src), "r"(bytes), "r"(mbar) : "memory");
}
#define MB_INIT(mb, c) asm volatile("mbarrier.init.shared.b64 [%0], %1;" :: "r"(mb), "r"((uint32_t)(c)) : "memory")
#define MB_EXPECT(mb, n) asm volatile("mbarrier.arrive.expect_tx.shared.b64 _, [%0], %1;" :: "r"(mb), "r"((uint32_t)(n)) : "memory")
#define MB_WAIT(mb, par) do {                                                    \
    uint32_t _m = (mb), _p = (par), _d;                                          \
    asm volatile("{\n\t.reg .pred p;\n\t"                                        \
        "mbarrier.try_wait.parity.acquire.cta.shared::cta.b64 p, [%1], %2;\n\t"  \
        "selp.b32 %0,1,0,p;\n\t}" : "=r"(_d) : "r"(_m), "r"(_p) : "memory");     \
    if (!_d) {                                                                   \
        asm volatile("{\n\t.reg .pred P1;\n\tWL_%=:\n\t"                         \
            "mbarrier.try_wait.parity.acquire.cta.shared::cta.b64 P1, [%0], %1, 0x989680;\n\t" \
            "@P1 bra.uni WD_%=;\n\tbra.uni WL_%=;\n\tWD_%=:\n\t}"                \
            :: "r"(_m), "r"(_p) : "memory");                                     \
    }                                                                            \
} while (0)

// ============ prep kernel 1: x -> swizzled fp16 tile images ============
__global__ void __launch_bounds__(TPB)
prep_x(const float* __restrict__ x)
{
    const int tt  = blockIdx.x >> 3;        // tile 0..127
    const int oct = blockIdx.x & 7;
    const int t   = threadIdx.x;
    const float4* gx = (const float4*)(x + (size_t)tt * 128 * 64);
    char* dh = gXH + (size_t)tt * 16384;
    #pragma unroll
    for (int i = 0; i < 2; i++) {
        int idx = oct * 256 + t + i * TPB;
        int r = idx >> 4, q = idx & 15;
        float4 v = gx[idx];
        int off = SW(r * 128 + q * 8);
        *(uint2*)(dh + off) = make_uint2(h2pack(v.x, v.y), h2pack(v.z, v.w));
    }
}

// == prep kernel 2: W1 (masked) / W2 -> swizzled fp16; W3 -> L3 B image ==
__global__ void __launch_bounds__(TPB)
prep_w(const float* __restrict__ W1, const float* __restrict__ W2,
       const float* __restrict__ W3)
{
    const int net = blockIdx.x;          // 0..62, k = net+1
    const int k   = net + 1;
    const int t   = threadIdx.x;
    const float4* g1 = (const float4*)(W1 + (size_t)net * 4096);
    const float4* g2 = (const float4*)(W2 + (size_t)net * 4096);
    char* d1 = gW1H + (size_t)net * 8192;
    char* d2 = gW2H + (size_t)net * 8192;
    #pragma unroll
    for (int i = 0; i < 8; i++) {
        int i4 = t + i * TPB;            // 0..1023; (j, 4 n's)
        int j = i4 >> 4, n4 = i4 & 15;
        float4 v1 = g1[i4];
        float4 v2 = g2[i4];
        if (j >= k) { v1.x = v1.y = v1.z = v1.w = 0.0f; }   // causal mask
        int off = SW(j * 128 + n4 * 8);
        *(uint2*)(d1 + off) = make_uint2(h2pack(v1.x, v1.y), h2pack(v1.z, v1.w));
        *(uint2*)(d2 + off) = make_uint2(h2pack(v2.x, v2.y), h2pack(v2.z, v2.w));
    }
    // W3 image: row j (h2 index) 32B: cols0,1 = W3[j][0..1] fp16, rest zero
    if (t < 64) {
        char* d3 = gW3F + (size_t)net * 2048 + t * 32;
        float a = W3[(size_t)net * 128 + 2 * t];
        float b = W3[(size_t)net * 128 + 2 * t + 1];
        *(uint4*)(d3)      = make_uint4(h2pack(a, b), 0u, 0u, 0u);
        *(uint4*)(d3 + 16) = make_uint4(0u, 0u, 0u, 0u);
    }
}

// ============================== main kernel ==================================
__global__ void __launch_bounds__(TPB, 3)
arnet_hmma9(const float* __restrict__ w0, const float* __restrict__ b0,
            const float* __restrict__ v0, const float* __restrict__ c0,
            const float* __restrict__ B1, const float* __restrict__ B2,
            const float* __restrict__ B3,
            float* __restrict__ out)
{
    extern __shared__ char smc[];
    const uint32_t sb = smem_u32(smc);
    const int t    = threadIdx.x;
    const int lane = t & 31;
    const int wrp  = t >> 5;
    const int qr   = lane >> 2;     // 0..7
    const int qc   = lane & 3;      // 0..3
    const int lm   = lane >> 3;     // ldmatrix sub-matrix id 0..3
    const int lr8  = lane & 7;      // ldmatrix row-within-matrix
    const int net  = blockIdx.y;    // network k = net+1
    const int k    = net + 1;
    const int kt1  = (k + 15) >> 4; // causal trim of layer-1 k-tiles
    const int tile0 = blockIdx.x * 4;   // four 128-row tiles per CTA

    // ---- staging: weights + x tiles 0,1 up-front on the 2-slot ring ----
    if (t == 0) {
        MB_INIT(sb + SO_MB0, 1);
        MB_INIT(sb + SO_MB1, 1);
        const uint32_t w1b = (uint32_t)kt1 * 2048;   // only rows layer-1 reads
        MB_EXPECT(sb + SO_MB0, 16384 + w1b + 8192 + 2048);
        bulk_cp(sb + SO_XH0, gXH  + (size_t)tile0 * 16384, 16384, sb + SO_MB0);
        bulk_cp(sb + SO_W1,  gW1H + (size_t)net * 8192,  w1b, sb + SO_MB0);
        bulk_cp(sb + SO_W2,  gW2H + (size_t)net * 8192,  8192, sb + SO_MB0);
        bulk_cp(sb + SO_W3F, gW3F + (size_t)net * 2048,  2048, sb + SO_MB0);
        MB_EXPECT(sb + SO_MB1, 16384);
        bulk_cp(sb + SO_XH1, gXH + (size_t)(tile0 + 1) * 16384, 16384, sb + SO_MB1);
    }
    if (t < 64) {
        ((float*)(smc + SO_B1))[t] = B1[net * 64 + t];
        ((float*)(smc + SO_B2))[t] = B2[net * 64 + t];
    }
    if (t == 64)
        *((float2*)(smc + SO_B3)) = make_float2(B3[net * 2], B3[net * 2 + 1]);
    __syncthreads();

    const float* b1s = (const float*)(smc + SO_B1);
    const float* b2s = (const float*)(smc + SO_B2);
    const float2 b3  = *(const float2*)(smc + SO_B3);

    #define A_ADDR(xbase, m, kt) \
        (sb + (xbase) + SW((wrp * 32 + (m) * 16 + (lm & 1) * 8 + lr8) * 128 + (kt) * 32 + (lm >> 1) * 16))
    #define B_ADDR(base, kt, p) \
        (sb + (base) + SW(((kt) * 16 + (lm & 1) * 8 + lr8) * 128 + ((p) * 2 + (lm >> 1)) * 16))

    #pragma unroll 1
    for (int i = 0; i < 4; i++) {
        const uint32_t xbase = (i & 1) ? SO_XH1 : SO_XH0;
        const uint32_t mb    = (i & 1) ? (sb + SO_MB1) : (sb + SO_MB0);
        MB_WAIT(mb, (i >> 1) & 1);
        const int brow0 = (tile0 + i) * TPB;

        // ====== layer 1: D1 = x[:, :k] @ W1 + B1 (single fp16 pass) ======
        float D1[2][8][4];          // [m][n-tile][frag]
        #pragma unroll
        for (int n = 0; n < 8; n++) {
            float bx = b1s[n * 8 + qc * 2], by = b1s[n * 8 + qc * 2 + 1];
            #pragma unroll
            for (int m = 0; m < 2; m++) {
                D1[m][n][0] = bx; D1[m][n][1] = by; D1[m][n][2] = bx; D1[m][n][3] = by;
            }
        }
        for (int kt = 0; kt < kt1; kt++) {
            uint32_t a[2][4];
            ldsm_x4(a[0], A_ADDR(xbase, 0, kt));
            ldsm_x4(a[1], A_ADDR(xbase, 1, kt));
            #pragma unroll
            for (int p = 0; p < 4; p++) {
                uint32_t bh[4];
                ldsm_x4t(bh, B_ADDR(SO_W1, kt, p));
                #pragma unroll
                for (int m = 0; m < 2; m++) {
                    mma16816(D1[m][2 * p],     a[m], bh[0], bh[1]);
                    mma16816(D1[m][2 * p + 1], a[m], bh[2], bh[3]);
                }
            }
        }

        // ---- relu + fp16-round D1 -> layer-2 A fragments ----
        uint32_t a2[4][2][4];       // [kt][m][frag]
        #pragma unroll
        for (int kt = 0; kt < 4; kt++) {
            #pragma unroll
            for (int m = 0; m < 2; m++) {
                a2[kt][m][0] = h2pack(fmaxf(D1[m][2*kt  ][0], 0.f), fmaxf(D1[m][2*kt  ][1], 0.f));
                a2[kt][m][1] = h2pack(fmaxf(D1[m][2*kt  ][2], 0.f), fmaxf(D1[m][2*kt  ][3], 0.f));
                a2[kt][m][2] = h2pack(fmaxf(D1[m][2*kt+1][0], 0.f), fmaxf(D1[m][2*kt+1][1], 0.f));
                a2[kt][m][3] = h2pack(fmaxf(D1[m][2*kt+1][2], 0.f), fmaxf(D1[m][2*kt+1][3], 0.f));
            }
        }

        // ---- all x reads for tile i are done: release slot, prefetch i+2 ----
        __syncthreads();
        if (t == 0 && i < 2) {
            MB_EXPECT(mb, 16384);
            bulk_cp(sb + xbase, gXH + (size_t)(tile0 + i + 2) * 16384, 16384, mb);
        }

        // ====== layer 2 + MMA layer 3: n-pair p of L2 == k-tile p of L3 ======
        float D3[2][4];             // [m][frag]; cols 0,1 = (out0,out1)
        #pragma unroll
        for (int m = 0; m < 2; m++) {
            D3[m][0] = b3.x; D3[m][1] = b3.y; D3[m][2] = b3.x; D3[m][3] = b3.y;
        }
        #pragma unroll
        for (int p = 0; p < 4; p++) {
            float D2[2][2][4];       // [m][n-subtile][frag]
            #pragma unroll
            for (int q = 0; q < 2; q++) {
                int n = 2 * p + q;
                float bx = b2s[n * 8 + qc * 2], by = b2s[n * 8 + qc * 2 + 1];
                #pragma unroll
                for (int m = 0; m < 2; m++) {
                    D2[m][q][0] = bx; D2[m][q][1] = by; D2[m][q][2] = bx; D2[m][q][3] = by;
                }
            }
            #pragma unroll
            for (int kt = 0; kt < 4; kt++) {
                uint32_t bh[4];
                ldsm_x4t(bh, B_ADDR(SO_W2, kt, p));
                #pragma unroll
                for (int m = 0; m < 2; m++) {
                    mma16816(D2[m][0], a2[kt][m], bh[0], bh[1]);
                    mma16816(D2[m][1], a2[kt][m], bh[2], bh[3]);
                }
            }
            // relu + pack -> L3 A-fragment for k-tile p; fold into D3 via MMA
            uint32_t b3f[4];
            ldsm_x4t(b3f, sb + SO_W3F + (p * 16 + (lm & 1) * 8 + lr8) * 32 + (lm >> 1) * 16);
            #pragma unroll
            for (int m = 0; m < 2; m++) {
                uint32_t a3[4];
                a3[0] = h2pack(fmaxf(D2[m][0][0], 0.f), fmaxf(D2[m][0][1], 0.f));
                a3[1] = h2pack(fmaxf(D2[m][0][2], 0.f), fmaxf(D2[m][0][3], 0.f));
                a3[2] = h2pack(fmaxf(D2[m][1][0], 0.f), fmaxf(D2[m][1][1], 0.f));
                a3[3] = h2pack(fmaxf(D2[m][1][2], 0.f), fmaxf(D2[m][1][3], 0.f));
                mma16816(D3[m], a3, b3f[0], b3f[1]);
            }
        }

        // ---- store: qc==0 lanes hold cols 0,1 = (out0,out1) ----
        if (qc == 0) {
            #pragma unroll
            for (int m = 0; m < 2; m++) {
                int brow = brow0 + wrp * 32 + m * 16 + qr;
                out[(size_t)brow * 64 + k] = fminf(fmaxf(D3[m][0], -5.0f), 5.0f);
                out[(size_t)(BATCHN + brow) * 64 + k] = D3[m][1];
                out[(size_t)(brow + 8) * 64 + k] = fminf(fmaxf(D3[m][2], -5.0f), 5.0f);
                out[(size_t)(BATCHN + brow + 8) * 64 + k] = D3[m][3];
            }
        }

        // ---- network 0: constant column (net==0 CTAs only) ----
        if (net == 0) {
            float s0 = c0[0], t0 = c0[1];
            #pragma unroll
            for (int h = 0; h < 64; h++) {
                float hv = fmaxf(w0[h] + b0[h], 0.0f);
                s0 = fmaf(hv, v0[2 * h],     s0);
                t0 = fmaf(hv, v0[2 * h + 1], t0);
            }
            const int brow = brow0 + t;
            out[(size_t)brow * 64] = fminf(fmaxf(s0, -5.0f), 5.0f);
            out[(size_t)(BATCHN + brow) * 64] = t0;
        }
    }
}

extern "C" void kernel_launch(void* const* d_in, const int* in_sizes, int n_in,
                              void* d_out, int out_size)
{
    (void)in_sizes; (void)n_in; (void)out_size;
    const float* x  = (const float*)d_in[0];
    const float* w0 = (const float*)d_in[1];
    const float* b0 = (const float*)d_in[2];
    const float* v0 = (const float*)d_in[3];
    const float* c0 = (const float*)d_in[4];
    const float* W1 = (const float*)d_in[5];
    const float* B1 = (const float*)d_in[6];
    const float* W2 = (const float*)d_in[7];
    const float* B2 = (const float*)d_in[8];
    const float* W3 = (const float*)d_in[9];
    const float* B3 = (const float*)d_in[10];
    float* out = (float*)d_out;

    cudaFuncSetAttribute(arnet_hmma9,
                         cudaFuncAttributeMaxDynamicSharedMemorySize, SMEM_BYTES);

    prep_x<<<1024, TPB>>>(x);
    prep_w<<<63, TPB>>>(W1, W2, W3);
    dim3 grid(BATCHN / (4 * TPB), 63);   // (32, 63), 512 rows per CTA
    arnet_hmma9<<<grid, TPB, SMEM_BYTES>>>(w0, b0, v0, c0,
                                           B1, B2, B3, out);
}